// round 5
// baseline (speedup 1.0000x reference)
#include <cuda_runtime.h>

// Problem constants
#define B_     2
#define T_     8
#define H_     14
#define W_     14
#define S_     196          // H_*W_
#define N_     1568         // T_*S_
#define DIM_   768
#define HEADS_ 12
#define HD_    64
#define MROWS  (B_ * N_)    // 3136
#define NBIAS  36           // 14 (h) + 14 (w) + 8 (t)

// Scratch (device globals; no runtime allocation allowed)
__device__ float g_q[(size_t)B_ * HEADS_ * N_ * HD_];
__device__ float g_k[(size_t)B_ * HEADS_ * N_ * HD_];
__device__ float g_v[(size_t)B_ * HEADS_ * N_ * HD_];
__device__ float g_bias[(size_t)B_ * HEADS_ * N_ * NBIAS];
__device__ float g_o[(size_t)MROWS * DIM_];

// ---------------------------------------------------------------------------
// QKV GEMM:  qkv[m, o] = sum_k x[m,k] * qkv_w[o,k]
// Scatters output directly into q/k/v with layout [b][head][n][d].
// M = 3136 (49 tiles of 64), N = 2304 (36 tiles of 64), K = 768.
// ---------------------------------------------------------------------------
__global__ __launch_bounds__(256) void qkv_gemm(const float* __restrict__ x,
                                                const float* __restrict__ w) {
    __shared__ float As[16][65];
    __shared__ float Ws[16][65];
    const int tid = threadIdx.x;
    const int tx = tid & 15, ty = tid >> 4;
    const int row0 = blockIdx.y * 64;
    const int col0 = blockIdx.x * 64;
    const int lr = tid >> 2;          // 0..63
    const int lk = (tid & 3) * 4;     // 0,4,8,12

    const float* Ar = x + (size_t)(row0 + lr) * DIM_ + lk;
    const float* Wr = w + (size_t)(col0 + lr) * DIM_ + lk;

    float acc[4][4];
#pragma unroll
    for (int i = 0; i < 4; i++)
#pragma unroll
        for (int j = 0; j < 4; j++) acc[i][j] = 0.f;

    for (int k0 = 0; k0 < DIM_; k0 += 16) {
        float4 a4 = *(const float4*)(Ar + k0);
        float4 w4 = *(const float4*)(Wr + k0);
        As[lk + 0][lr] = a4.x; As[lk + 1][lr] = a4.y;
        As[lk + 2][lr] = a4.z; As[lk + 3][lr] = a4.w;
        Ws[lk + 0][lr] = w4.x; Ws[lk + 1][lr] = w4.y;
        Ws[lk + 2][lr] = w4.z; Ws[lk + 3][lr] = w4.w;
        __syncthreads();
#pragma unroll
        for (int kk = 0; kk < 16; kk++) {
            float a[4], b[4];
#pragma unroll
            for (int i = 0; i < 4; i++) a[i] = As[kk][ty * 4 + i];
#pragma unroll
            for (int j = 0; j < 4; j++) b[j] = Ws[kk][tx * 4 + j];
#pragma unroll
            for (int i = 0; i < 4; i++)
#pragma unroll
                for (int j = 0; j < 4; j++) acc[i][j] += a[i] * b[j];
        }
        __syncthreads();
    }

    // Whole 64-wide col tile lies in a single (s, head) slot (64-aligned).
    const int s    = col0 / DIM_;            // 0=q, 1=k, 2=v
    const int head = (col0 % DIM_) / HD_;
    float* dst = (s == 0) ? g_q : (s == 1) ? g_k : g_v;
#pragma unroll
    for (int i = 0; i < 4; i++) {
        int mm = row0 + ty * 4 + i;
        int bb = mm / N_;
        int nn = mm - bb * N_;
        float* drow = dst + (((size_t)bb * HEADS_ + head) * N_ + nn) * HD_;
#pragma unroll
        for (int j = 0; j < 4; j++) drow[tx * 4 + j] = acc[i][j];
    }
}

// ---------------------------------------------------------------------------
// Relative position bias precompute:
//   bias[(b,h,q)][0..13]  = dot(q_vec, rel_pos_h[qh - j + 13])
//   bias[(b,h,q)][14..27] = dot(q_vec, rel_pos_w[qw - j + 13])
//   bias[(b,h,q)][28..35] = dot(q_vec, rel_pos_t[qt - j + 7])
// One warp per (b,h,q). q_vec is the UNscaled q (matches reference).
// ---------------------------------------------------------------------------
__global__ __launch_bounds__(256) void relbias(const float* __restrict__ rel_h,
                                               const float* __restrict__ rel_w,
                                               const float* __restrict__ rel_t) {
    const int warp = (blockIdx.x * blockDim.x + threadIdx.x) >> 5;
    const int lane = threadIdx.x & 31;
    if (warp >= B_ * HEADS_ * N_) return;
    const int q = warp % N_;
    const int qt = q / S_;
    const int qrem = q - qt * S_;
    const int qh = qrem / W_;
    const int qw = qrem - qh * W_;

    const float* qv = g_q + (size_t)warp * HD_;
    const float qa = qv[lane];
    const float qb = qv[lane + 32];
    float* out = g_bias + (size_t)warp * NBIAS;

#pragma unroll 4
    for (int j = 0; j < NBIAS; j++) {
        const float* r;
        if (j < 14)       r = rel_h + (size_t)(qh - j + 13) * HD_;
        else if (j < 28)  r = rel_w + (size_t)(qw - (j - 14) + 13) * HD_;
        else              r = rel_t + (size_t)(qt - (j - 28) + 7) * HD_;
        float p = qa * r[lane] + qb * r[lane + 32];
#pragma unroll
        for (int m = 16; m >= 1; m >>= 1) p += __shfl_xor_sync(0xffffffffu, p, m);
        if (lane == 0) out[j] = p;
    }
}

// ---------------------------------------------------------------------------
// Fused attention: for each (b, head, 64-query tile):
//   scores = (Q*scale) @ K^T + bias_h[q,kh] + bias_w[q,kw] + bias_t[q,kt]
//   online softmax over k; O = P @ V; write O/l to g_o as [b][n][head*64+d].
// Threads: 16x16, each owns 4q x 4k (score stage) and 4q x 4d (PV stage).
// ---------------------------------------------------------------------------
#define ATTN_SMEM ((4 * 4096 + 64 * NBIAS) * sizeof(float))   // 74,752 B

__global__ __launch_bounds__(256) void attn_kernel() {
    extern __shared__ float sm[];
    float* Qt = sm;                 // [64 d][64 q]  (pre-scaled)
    float* Kt = sm + 4096;          // [64 d][64 k]
    float* Vs = sm + 8192;          // [64 k][64 d]
    float* Ps = sm + 12288;         // [64 q][64 k]
    float* Bi = sm + 16384;         // [64 q][36]

    const int b  = blockIdx.z;
    const int h  = blockIdx.y;
    const int q0 = blockIdx.x * 64;
    const int tid = threadIdx.x;
    const int tx = tid & 15, ty = tid >> 4;
    const int lr = tid >> 2;          // row within tile 0..63
    const int l4 = (tid & 3) * 16;    // 16-float chunk base

    const size_t base = ((size_t)b * HEADS_ + h) * N_ * HD_;
    const float* Qp = g_q + base;
    const float* Kp = g_k + base;
    const float* Vp = g_v + base;
    const float scale = 0.125f;       // 64^-0.5

    // Load Q tile transposed + pre-scaled
    {
        int qg = q0 + lr;
        bool ok = qg < N_;
        const float* src = Qp + (size_t)(ok ? qg : 0) * HD_;
#pragma unroll
        for (int u = 0; u < 4; u++) {
            int d = l4 + u * 4;
            float4 v4 = make_float4(0.f, 0.f, 0.f, 0.f);
            if (ok) v4 = *(const float4*)(src + d);
            Qt[(d + 0) * 64 + lr] = v4.x * scale;
            Qt[(d + 1) * 64 + lr] = v4.y * scale;
            Qt[(d + 2) * 64 + lr] = v4.z * scale;
            Qt[(d + 3) * 64 + lr] = v4.w * scale;
        }
    }
    // Load the 36-entry bias rows for this q tile
    for (int i = tid; i < 64 * NBIAS; i += 256) {
        int ql = i / NBIAS;
        int qg = q0 + ql;
        Bi[i] = (qg < N_)
            ? g_bias[(((size_t)b * HEADS_ + h) * N_ + qg) * NBIAS + (i - ql * NBIAS)]
            : 0.f;
    }

    float m_row[4], l_row[4], o_acc[4][4];
#pragma unroll
    for (int i = 0; i < 4; i++) {
        m_row[i] = -1e30f;
        l_row[i] = 0.f;
#pragma unroll
        for (int j = 0; j < 4; j++) o_acc[i][j] = 0.f;
    }

    for (int k0 = 0; k0 < N_; k0 += 64) {
        __syncthreads();   // previous iter's smem reads complete
        {
            int kg = k0 + lr;
            bool ok = kg < N_;
            const float* ks = Kp + (size_t)(ok ? kg : 0) * HD_;
            const float* vs = Vp + (size_t)(ok ? kg : 0) * HD_;
#pragma unroll
            for (int u = 0; u < 4; u++) {
                int d = l4 + u * 4;
                float4 kv = make_float4(0.f, 0.f, 0.f, 0.f);
                float4 vv = make_float4(0.f, 0.f, 0.f, 0.f);
                if (ok) {
                    kv = *(const float4*)(ks + d);
                    vv = *(const float4*)(vs + d);
                }
                Kt[(d + 0) * 64 + lr] = kv.x;
                Kt[(d + 1) * 64 + lr] = kv.y;
                Kt[(d + 2) * 64 + lr] = kv.z;
                Kt[(d + 3) * 64 + lr] = kv.w;
                *(float4*)(Vs + lr * 64 + d) = vv;
            }
        }
        __syncthreads();

        // Score tile: s[i][j] = (scaled q_i) . k_j
        float s[4][4];
#pragma unroll
        for (int i = 0; i < 4; i++)
#pragma unroll
            for (int j = 0; j < 4; j++) s[i][j] = 0.f;
#pragma unroll 8
        for (int d = 0; d < 64; d++) {
            float4 aq = *(const float4*)(Qt + d * 64 + ty * 4);
            float4 bk = *(const float4*)(Kt + d * 64 + tx * 4);
            float a[4] = {aq.x, aq.y, aq.z, aq.w};
            float bb[4] = {bk.x, bk.y, bk.z, bk.w};
#pragma unroll
            for (int i = 0; i < 4; i++)
#pragma unroll
                for (int j = 0; j < 4; j++) s[i][j] += a[i] * bb[j];
        }

        // Add decomposed rel-pos bias; mask invalid k
#pragma unroll
        for (int j = 0; j < 4; j++) {
            int kg = k0 + tx * 4 + j;
            if (kg < N_) {
                int kt = kg / S_;
                int krem = kg - kt * S_;
                int kh = krem / W_;
                int kw = krem - kh * W_;
#pragma unroll
                for (int i = 0; i < 4; i++) {
                    const float* br = Bi + (ty * 4 + i) * NBIAS;
                    s[i][j] += br[kh] + br[14 + kw] + br[28 + kt];
                }
            } else {
#pragma unroll
                for (int i = 0; i < 4; i++) s[i][j] = -1e30f;
            }
        }

        // Online softmax update (row stats reduced across the 16 tx lanes)
#pragma unroll
        for (int i = 0; i < 4; i++) {
            float mb = fmaxf(fmaxf(s[i][0], s[i][1]), fmaxf(s[i][2], s[i][3]));
#pragma unroll
            for (int m = 1; m < 16; m <<= 1)
                mb = fmaxf(mb, __shfl_xor_sync(0xffffffffu, mb, m));
            float mn = fmaxf(m_row[i], mb);
            float c = __expf(m_row[i] - mn);
            m_row[i] = mn;
            float rs = 0.f;
#pragma unroll
            for (int j = 0; j < 4; j++) {
                s[i][j] = __expf(s[i][j] - mn);
                rs += s[i][j];
            }
#pragma unroll
            for (int m = 1; m < 16; m <<= 1)
                rs += __shfl_xor_sync(0xffffffffu, rs, m);
            l_row[i] = l_row[i] * c + rs;
#pragma unroll
            for (int j = 0; j < 4; j++) o_acc[i][j] *= c;
            *(float4*)(Ps + (ty * 4 + i) * 64 + tx * 4) =
                make_float4(s[i][0], s[i][1], s[i][2], s[i][3]);
        }
        __syncthreads();

        // O += P @ V  (thread owns 4q x 4d)
#pragma unroll 8
        for (int kk = 0; kk < 64; kk++) {
            float p0 = Ps[(ty * 4 + 0) * 64 + kk];
            float p1 = Ps[(ty * 4 + 1) * 64 + kk];
            float p2 = Ps[(ty * 4 + 2) * 64 + kk];
            float p3 = Ps[(ty * 4 + 3) * 64 + kk];
            float4 v4 = *(const float4*)(Vs + kk * 64 + tx * 4);
            o_acc[0][0] += p0 * v4.x; o_acc[0][1] += p0 * v4.y;
            o_acc[0][2] += p0 * v4.z; o_acc[0][3] += p0 * v4.w;
            o_acc[1][0] += p1 * v4.x; o_acc[1][1] += p1 * v4.y;
            o_acc[1][2] += p1 * v4.z; o_acc[1][3] += p1 * v4.w;
            o_acc[2][0] += p2 * v4.x; o_acc[2][1] += p2 * v4.y;
            o_acc[2][2] += p2 * v4.z; o_acc[2][3] += p2 * v4.w;
            o_acc[3][0] += p3 * v4.x; o_acc[3][1] += p3 * v4.y;
            o_acc[3][2] += p3 * v4.z; o_acc[3][3] += p3 * v4.w;
        }
    }

    // Epilogue: O / l → g_o laid out [b][n][head*64 + d]
#pragma unroll
    for (int i = 0; i < 4; i++) {
        int qg = q0 + ty * 4 + i;
        if (qg < N_) {
            float inv = 1.f / l_row[i];
            float* orow = g_o + ((size_t)b * N_ + qg) * DIM_ + h * HD_;
#pragma unroll
            for (int j = 0; j < 4; j++) orow[tx * 4 + j] = o_acc[i][j] * inv;
        }
    }
}

// ---------------------------------------------------------------------------
// Output projection: out[m, o] = sum_c g_o[m,c] * proj_w[o,c] + proj_b[o]
// M = 3136, N = 768 (12 tiles of 64), K = 768.
// ---------------------------------------------------------------------------
__global__ __launch_bounds__(256) void proj_gemm(const float* __restrict__ w,
                                                 const float* __restrict__ pb,
                                                 float* __restrict__ out) {
    __shared__ float As[16][65];
    __shared__ float Ws[16][65];
    const int tid = threadIdx.x;
    const int tx = tid & 15, ty = tid >> 4;
    const int row0 = blockIdx.y * 64;
    const int col0 = blockIdx.x * 64;
    const int lr = tid >> 2;
    const int lk = (tid & 3) * 4;

    const float* Ar = g_o + (size_t)(row0 + lr) * DIM_ + lk;
    const float* Wr = w + (size_t)(col0 + lr) * DIM_ + lk;

    float acc[4][4];
#pragma unroll
    for (int i = 0; i < 4; i++)
#pragma unroll
        for (int j = 0; j < 4; j++) acc[i][j] = 0.f;

    for (int k0 = 0; k0 < DIM_; k0 += 16) {
        float4 a4 = *(const float4*)(Ar + k0);
        float4 w4 = *(const float4*)(Wr + k0);
        As[lk + 0][lr] = a4.x; As[lk + 1][lr] = a4.y;
        As[lk + 2][lr] = a4.z; As[lk + 3][lr] = a4.w;
        Ws[lk + 0][lr] = w4.x; Ws[lk + 1][lr] = w4.y;
        Ws[lk + 2][lr] = w4.z; Ws[lk + 3][lr] = w4.w;
        __syncthreads();
#pragma unroll
        for (int kk = 0; kk < 16; kk++) {
            float a[4], b[4];
#pragma unroll
            for (int i = 0; i < 4; i++) a[i] = As[kk][ty * 4 + i];
#pragma unroll
            for (int j = 0; j < 4; j++) b[j] = Ws[kk][tx * 4 + j];
#pragma unroll
            for (int i = 0; i < 4; i++)
#pragma unroll
                for (int j = 0; j < 4; j++) acc[i][j] += a[i] * b[j];
        }
        __syncthreads();
    }

#pragma unroll
    for (int i = 0; i < 4; i++) {
        int mm = row0 + ty * 4 + i;
        float* orow = out + (size_t)mm * DIM_ + col0;
#pragma unroll
        for (int j = 0; j < 4; j++) {
            int c = tx * 4 + j;
            orow[c] = acc[i][j] + pb[col0 + c];
        }
    }
}

// ---------------------------------------------------------------------------
extern "C" void kernel_launch(void* const* d_in, const int* in_sizes, int n_in,
                              void* d_out, int out_size) {
    (void)in_sizes; (void)n_in; (void)out_size;
    const float* x      = (const float*)d_in[0];
    const float* qkv_w  = (const float*)d_in[1];
    const float* proj_w = (const float*)d_in[2];
    const float* proj_b = (const float*)d_in[3];
    const float* rel_h  = (const float*)d_in[4];
    const float* rel_w  = (const float*)d_in[5];
    const float* rel_t  = (const float*)d_in[6];
    float* out = (float*)d_out;

    cudaFuncSetAttribute(attn_kernel,
                         cudaFuncAttributeMaxDynamicSharedMemorySize,
                         (int)ATTN_SMEM);

    // 1) QKV projection → q/k/v scratch (head-major)
    qkv_gemm<<<dim3(36, 49), 256>>>(x, qkv_w);

    // 2) Decomposed rel-pos bias tables (one warp per (b,h,q))
    relbias<<<(B_ * HEADS_ * N_ + 7) / 8, 256>>>(rel_h, rel_w, rel_t);

    // 3) Fused attention (scores + bias + softmax + PV)
    attn_kernel<<<dim3((N_ + 63) / 64, HEADS_, B_), 256, ATTN_SMEM>>>();

    // 4) Output projection + bias → d_out
    proj_gemm<<<dim3(12, 49), 256>>>(proj_w, proj_b, out);
}

// round 7
// speedup vs baseline: 1.5286x; 1.5286x over previous
#include <cuda_runtime.h>
#include <cuda_bf16.h>
#include <cstdint>

// Problem constants
#define B_     2
#define T_     8
#define H_     14
#define W_     14
#define S_     196          // H_*W_
#define N_     1568         // T_*S_
#define DIM_   768
#define HEADS_ 12
#define HD_    64
#define MROWS  (B_ * N_)    // 3136
#define MPAD   3200         // 25 * 128
#define NBIAS  36           // 14 (h) + 14 (w) + 8 (t)

// fp32 scratch
__device__ float g_q[(size_t)B_ * HEADS_ * N_ * HD_];
__device__ float g_k[(size_t)B_ * HEADS_ * N_ * HD_];
__device__ float g_v[(size_t)B_ * HEADS_ * N_ * HD_];
__device__ float g_bias[(size_t)B_ * HEADS_ * N_ * NBIAS];
__device__ float g_o[(size_t)MROWS * DIM_];

// split-bf16 scratch (hi/lo decomposition for tensor-core GEMMs)
__device__ __nv_bfloat16 g_xh[(size_t)MPAD * DIM_];
__device__ __nv_bfloat16 g_xl[(size_t)MPAD * DIM_];
__device__ __nv_bfloat16 g_wh[(size_t)3 * DIM_ * DIM_];
__device__ __nv_bfloat16 g_wl[(size_t)3 * DIM_ * DIM_];
__device__ __nv_bfloat16 g_ph[(size_t)DIM_ * DIM_];
__device__ __nv_bfloat16 g_pl[(size_t)DIM_ * DIM_];
__device__ __nv_bfloat16 g_oh[(size_t)MPAD * DIM_];
__device__ __nv_bfloat16 g_ol[(size_t)MPAD * DIM_];

// ---------------------------------------------------------------------------
// Helpers (sm_80-family features only: cp.async / ldmatrix / mma.sync — these
// compile to plain compute_103; NO tcgen05 (harness PTX target lacks 'a').
// ---------------------------------------------------------------------------
__device__ __forceinline__ uint32_t smem_u32(const void* p) {
    uint32_t a;
    asm("{ .reg .u64 t; cvta.to.shared.u64 t, %1; cvt.u32.u64 %0, t; }"
        : "=r"(a) : "l"(p));
    return a;
}

__device__ __forceinline__ uint32_t swz(uint32_t x) {
    return x ^ ((x >> 3) & 0x70);   // XOR 16B-chunk index with (row & 7)
}

#define CP_ASYNC16(s, g) \
    asm volatile("cp.async.cg.shared.global [%0], [%1], 16;" :: "r"(s), "l"(g))

#define LDSM4(r, a) \
    asm volatile("ldmatrix.sync.aligned.m8n8.x4.shared.b16 {%0,%1,%2,%3}, [%4];" \
        : "=r"((r)[0]), "=r"((r)[1]), "=r"((r)[2]), "=r"((r)[3]) : "r"(a))

#define MMA16816(d, a, b0, b1) \
    asm volatile("mma.sync.aligned.m16n8k16.row.col.f32.bf16.bf16.f32 " \
        "{%0,%1,%2,%3},{%4,%5,%6,%7},{%8,%9},{%0,%1,%2,%3};" \
        : "+f"((d)[0]), "+f"((d)[1]), "+f"((d)[2]), "+f"((d)[3]) \
        : "r"((a)[0]), "r"((a)[1]), "r"((a)[2]), "r"((a)[3]), "r"(b0), "r"(b1))

// ---------------------------------------------------------------------------
// Split conversion: v = bf16(v) + bf16(v - bf16(v)).  sel selects dst arrays.
// ---------------------------------------------------------------------------
__global__ __launch_bounds__(256) void split_convert(const float* __restrict__ src,
                                                     int sel, int n_src, int n_pad) {
    int i = blockIdx.x * blockDim.x + threadIdx.x;
    if (i >= n_pad) return;
    const float* s = (sel == 3) ? g_o : src;
    __nv_bfloat16 *hi, *lo;
    if (sel == 0)      { hi = g_xh; lo = g_xl; }
    else if (sel == 1) { hi = g_wh; lo = g_wl; }
    else if (sel == 2) { hi = g_ph; lo = g_pl; }
    else               { hi = g_oh; lo = g_ol; }
    float v = (i < n_src) ? s[i] : 0.f;
    __nv_bfloat16 h = __float2bfloat16(v);
    hi[i] = h;
    lo[i] = __float2bfloat16(v - __bfloat162float(h));
}

// ---------------------------------------------------------------------------
// Warp-MMA split-bf16 GEMM:  D[m,n] = sum_k A[m,k]*B[n,k]
// CTA tile 128x128, 8 warps (warp tile 32m x 64n), K chunks of 64.
// Per k16 step: 3 products Ah*Bh + Al*Bh + Ah*Bl (fp32 accum in regs).
// mode 0: A=x(hi/lo),  B=qkv_w(hi/lo), scatter into g_q/g_k/g_v (head-major).
// mode 1: A=g_o(hi/lo), B=proj_w(hi/lo), add proj_b, write out.
// Smem: 4 tiles of 128x64 bf16 (16KB each), SW128-style swizzle. 64KB total.
// ---------------------------------------------------------------------------
#define OFF_AH 0u
#define OFF_AL 16384u
#define OFF_BH 32768u
#define OFF_BL 49152u
#define GSMEM  65536

__global__ __launch_bounds__(256) void mma_gemm(int mode,
                                                const float* __restrict__ pb,
                                                float* __restrict__ out) {
    extern __shared__ char sm[];
    const uint32_t sb = smem_u32(sm);
    const int tid = threadIdx.x;
    const int lane = tid & 31, wid = tid >> 5;
    const int wm = wid & 3;        // 0..3 -> m offset wm*32
    const int wn = wid >> 2;       // 0..1 -> n offset wn*64
    const int m0 = blockIdx.y * 128;
    const int n0 = blockIdx.x * 128;

    const __nv_bfloat16* Ahp = (mode == 0) ? g_xh : g_oh;
    const __nv_bfloat16* Alp = (mode == 0) ? g_xl : g_ol;
    const __nv_bfloat16* Bhp = (mode == 0) ? g_wh : g_ph;
    const __nv_bfloat16* Blp = (mode == 0) ? g_wl : g_pl;

    float acc[2][8][4];
#pragma unroll
    for (int a = 0; a < 2; a++)
#pragma unroll
        for (int na = 0; na < 8; na++)
#pragma unroll
            for (int r = 0; r < 4; r++) acc[a][na][r] = 0.f;

    // ldmatrix lane address bases (byte offsets within a 128x64-bf16 tile;
    // tile rows are 128B).  A: lanes 0-15 -> rows, lane>>4 -> k-halves.
    const int ar = lane & 15, akh = lane >> 4;
    const uint32_t a_base = (uint32_t)((wm * 32 + ar) * 128 + akh * 16);
    // B: 4 groups of 8 lanes: (sel>>1)*8 rows, (sel&1)*8 k-cols.
    const int br = lane & 7, bsel = lane >> 3;
    const uint32_t b_base =
        (uint32_t)((wn * 64 + (bsel >> 1) * 8 + br) * 128 + (bsel & 1) * 16);

    // cp.async source/dest for this thread (4 passes of 256x16B per tile)
    const int grow = tid >> 3;          // 0..31 (+32 per pass)
    const int gch = tid & 7;            // 16B chunk in row

    for (int c = 0; c < DIM_ / 64; c++) {
        const int k0 = c * 64;
#pragma unroll
        for (int p = 0; p < 4; p++) {
            int row = grow + p * 32;
            uint32_t sw = swz((uint32_t)(row * 128 + gch * 16));
            size_t ga = (size_t)(m0 + row) * DIM_ + k0 + gch * 8;
            size_t gb = (size_t)(n0 + row) * DIM_ + k0 + gch * 8;
            CP_ASYNC16(sb + OFF_AH + sw, Ahp + ga);
            CP_ASYNC16(sb + OFF_AL + sw, Alp + ga);
            CP_ASYNC16(sb + OFF_BH + sw, Bhp + gb);
            CP_ASYNC16(sb + OFF_BL + sw, Blp + gb);
        }
        asm volatile("cp.async.commit_group;");
        asm volatile("cp.async.wait_group 0;" ::: "memory");
        __syncthreads();

#pragma unroll
        for (int ks = 0; ks < 4; ks++) {
            const uint32_t kb = ks * 32;   // byte offset of k-step in row
            uint32_t ah[2][4], bh[4][4];
#pragma unroll
            for (int a = 0; a < 2; a++)
                LDSM4(ah[a], sb + OFF_AH + swz(a_base + a * 2048 + kb));
#pragma unroll
            for (int g = 0; g < 4; g++)
                LDSM4(bh[g], sb + OFF_BH + swz(b_base + g * 2048 + kb));
            // Ah * Bh
#pragma unroll
            for (int a = 0; a < 2; a++)
#pragma unroll
                for (int g = 0; g < 4; g++) {
                    MMA16816(acc[a][2 * g + 0], ah[a], bh[g][0], bh[g][1]);
                    MMA16816(acc[a][2 * g + 1], ah[a], bh[g][2], bh[g][3]);
                }
            // Al * Bh
            {
                uint32_t al[2][4];
#pragma unroll
                for (int a = 0; a < 2; a++)
                    LDSM4(al[a], sb + OFF_AL + swz(a_base + a * 2048 + kb));
#pragma unroll
                for (int a = 0; a < 2; a++)
#pragma unroll
                    for (int g = 0; g < 4; g++) {
                        MMA16816(acc[a][2 * g + 0], al[a], bh[g][0], bh[g][1]);
                        MMA16816(acc[a][2 * g + 1], al[a], bh[g][2], bh[g][3]);
                    }
            }
            // Ah * Bl (reuse bh storage)
#pragma unroll
            for (int g = 0; g < 4; g++)
                LDSM4(bh[g], sb + OFF_BL + swz(b_base + g * 2048 + kb));
#pragma unroll
            for (int a = 0; a < 2; a++)
#pragma unroll
                for (int g = 0; g < 4; g++) {
                    MMA16816(acc[a][2 * g + 0], ah[a], bh[g][0], bh[g][1]);
                    MMA16816(acc[a][2 * g + 1], ah[a], bh[g][2], bh[g][3]);
                }
        }
        __syncthreads();
    }

    // Epilogue. Fragment c: c0,c1 -> (row = lane/4, col = 2*(lane%4)+{0,1}),
    //                       c2,c3 -> row+8.
    const int mr = m0 + wm * 32 + lane / 4;
    const int nc0 = (lane & 3) * 2;
    if (mode == 0) {
        const int ncb = n0 + wn * 64;
        const int s = ncb / DIM_;                 // 0=q,1=k,2=v
        const int head = (ncb % DIM_) / HD_;
        float* dst = (s == 0) ? g_q : (s == 1) ? g_k : g_v;
#pragma unroll
        for (int a = 0; a < 2; a++)
#pragma unroll
            for (int hf = 0; hf < 2; hf++) {
                int m = mr + a * 16 + hf * 8;
                if (m < MROWS) {
                    int bb = m / N_;
                    int nn = m - bb * N_;
                    float* drow = dst + (((size_t)bb * HEADS_ + head) * N_ + nn) * HD_;
#pragma unroll
                    for (int na = 0; na < 8; na++)
                        *(float2*)(drow + na * 8 + nc0) =
                            make_float2(acc[a][na][hf * 2], acc[a][na][hf * 2 + 1]);
                }
            }
    } else {
        const int ncb = n0 + wn * 64;
#pragma unroll
        for (int a = 0; a < 2; a++)
#pragma unroll
            for (int hf = 0; hf < 2; hf++) {
                int m = mr + a * 16 + hf * 8;
                if (m < MROWS) {
                    float* orow = out + (size_t)m * DIM_ + ncb;
#pragma unroll
                    for (int na = 0; na < 8; na++) {
                        int cc = na * 8 + nc0;
                        orow[cc]     = acc[a][na][hf * 2]     + pb[ncb + cc];
                        orow[cc + 1] = acc[a][na][hf * 2 + 1] + pb[ncb + cc + 1];
                    }
                }
            }
    }
}

// ---------------------------------------------------------------------------
// Relative position bias precompute (one warp per (b,h,q)).
// ---------------------------------------------------------------------------
__global__ __launch_bounds__(256) void relbias(const float* __restrict__ rel_h,
                                               const float* __restrict__ rel_w,
                                               const float* __restrict__ rel_t) {
    const int warp = (blockIdx.x * blockDim.x + threadIdx.x) >> 5;
    const int lane = threadIdx.x & 31;
    if (warp >= B_ * HEADS_ * N_) return;
    const int q = warp % N_;
    const int qt = q / S_;
    const int qrem = q - qt * S_;
    const int qh = qrem / W_;
    const int qw = qrem - qh * W_;

    const float* qv = g_q + (size_t)warp * HD_;
    const float qa = qv[lane];
    const float qb = qv[lane + 32];
    float* out = g_bias + (size_t)warp * NBIAS;

#pragma unroll 4
    for (int j = 0; j < NBIAS; j++) {
        const float* r;
        if (j < 14)       r = rel_h + (size_t)(qh - j + 13) * HD_;
        else if (j < 28)  r = rel_w + (size_t)(qw - (j - 14) + 13) * HD_;
        else              r = rel_t + (size_t)(qt - (j - 28) + 7) * HD_;
        float p = qa * r[lane] + qb * r[lane + 32];
#pragma unroll
        for (int m = 16; m >= 1; m >>= 1) p += __shfl_xor_sync(0xffffffffu, p, m);
        if (lane == 0) out[j] = p;
    }
}

// ---------------------------------------------------------------------------
// Fused attention (fp32 SIMT, unchanged).
// ---------------------------------------------------------------------------
#define ATTN_SMEM ((4 * 4096 + 64 * NBIAS) * sizeof(float))   // 74,752 B

__global__ __launch_bounds__(256) void attn_kernel() {
    extern __shared__ float smf[];
    float* Qt = smf;                 // [64 d][64 q]  (pre-scaled)
    float* Kt = smf + 4096;          // [64 d][64 k]
    float* Vs = smf + 8192;          // [64 k][64 d]
    float* Ps = smf + 12288;         // [64 q][64 k]
    float* Bi = smf + 16384;         // [64 q][36]

    const int b  = blockIdx.z;
    const int h  = blockIdx.y;
    const int q0 = blockIdx.x * 64;
    const int tid = threadIdx.x;
    const int tx = tid & 15, ty = tid >> 4;
    const int lr = tid >> 2;
    const int l4 = (tid & 3) * 16;

    const size_t base = ((size_t)b * HEADS_ + h) * N_ * HD_;
    const float* Qp = g_q + base;
    const float* Kp = g_k + base;
    const float* Vp = g_v + base;
    const float scale = 0.125f;

    {
        int qg = q0 + lr;
        bool ok = qg < N_;
        const float* src = Qp + (size_t)(ok ? qg : 0) * HD_;
#pragma unroll
        for (int u = 0; u < 4; u++) {
            int d = l4 + u * 4;
            float4 v4 = make_float4(0.f, 0.f, 0.f, 0.f);
            if (ok) v4 = *(const float4*)(src + d);
            Qt[(d + 0) * 64 + lr] = v4.x * scale;
            Qt[(d + 1) * 64 + lr] = v4.y * scale;
            Qt[(d + 2) * 64 + lr] = v4.z * scale;
            Qt[(d + 3) * 64 + lr] = v4.w * scale;
        }
    }
    for (int i = tid; i < 64 * NBIAS; i += 256) {
        int ql = i / NBIAS;
        int qg = q0 + ql;
        Bi[i] = (qg < N_)
            ? g_bias[(((size_t)b * HEADS_ + h) * N_ + qg) * NBIAS + (i - ql * NBIAS)]
            : 0.f;
    }

    float m_row[4], l_row[4], o_acc[4][4];
#pragma unroll
    for (int i = 0; i < 4; i++) {
        m_row[i] = -1e30f;
        l_row[i] = 0.f;
#pragma unroll
        for (int j = 0; j < 4; j++) o_acc[i][j] = 0.f;
    }

    for (int k0 = 0; k0 < N_; k0 += 64) {
        __syncthreads();
        {
            int kg = k0 + lr;
            bool ok = kg < N_;
            const float* ks = Kp + (size_t)(ok ? kg : 0) * HD_;
            const float* vs = Vp + (size_t)(ok ? kg : 0) * HD_;
#pragma unroll
            for (int u = 0; u < 4; u++) {
                int d = l4 + u * 4;
                float4 kv = make_float4(0.f, 0.f, 0.f, 0.f);
                float4 vv = make_float4(0.f, 0.f, 0.f, 0.f);
                if (ok) {
                    kv = *(const float4*)(ks + d);
                    vv = *(const float4*)(vs + d);
                }
                Kt[(d + 0) * 64 + lr] = kv.x;
                Kt[(d + 1) * 64 + lr] = kv.y;
                Kt[(d + 2) * 64 + lr] = kv.z;
                Kt[(d + 3) * 64 + lr] = kv.w;
                *(float4*)(Vs + lr * 64 + d) = vv;
            }
        }
        __syncthreads();

        float s[4][4];
#pragma unroll
        for (int i = 0; i < 4; i++)
#pragma unroll
            for (int j = 0; j < 4; j++) s[i][j] = 0.f;
#pragma unroll 8
        for (int d = 0; d < 64; d++) {
            float4 aq = *(const float4*)(Qt + d * 64 + ty * 4);
            float4 bk = *(const float4*)(Kt + d * 64 + tx * 4);
            float a[4] = {aq.x, aq.y, aq.z, aq.w};
            float bb[4] = {bk.x, bk.y, bk.z, bk.w};
#pragma unroll
            for (int i = 0; i < 4; i++)
#pragma unroll
                for (int j = 0; j < 4; j++) s[i][j] += a[i] * bb[j];
        }

#pragma unroll
        for (int j = 0; j < 4; j++) {
            int kg = k0 + tx * 4 + j;
            if (kg < N_) {
                int kt = kg / S_;
                int krem = kg - kt * S_;
                int kh = krem / W_;
                int kw = krem - kh * W_;
#pragma unroll
                for (int i = 0; i < 4; i++) {
                    const float* br = Bi + (ty * 4 + i) * NBIAS;
                    s[i][j] += br[kh] + br[14 + kw] + br[28 + kt];
                }
            } else {
#pragma unroll
                for (int i = 0; i < 4; i++) s[i][j] = -1e30f;
            }
        }

#pragma unroll
        for (int i = 0; i < 4; i++) {
            float mb = fmaxf(fmaxf(s[i][0], s[i][1]), fmaxf(s[i][2], s[i][3]));
#pragma unroll
            for (int m = 1; m < 16; m <<= 1)
                mb = fmaxf(mb, __shfl_xor_sync(0xffffffffu, mb, m));
            float mn = fmaxf(m_row[i], mb);
            float cf = __expf(m_row[i] - mn);
            m_row[i] = mn;
            float rs = 0.f;
#pragma unroll
            for (int j = 0; j < 4; j++) {
                s[i][j] = __expf(s[i][j] - mn);
                rs += s[i][j];
            }
#pragma unroll
            for (int m = 1; m < 16; m <<= 1)
                rs += __shfl_xor_sync(0xffffffffu, rs, m);
            l_row[i] = l_row[i] * cf + rs;
#pragma unroll
            for (int j = 0; j < 4; j++) o_acc[i][j] *= cf;
            *(float4*)(Ps + (ty * 4 + i) * 64 + tx * 4) =
                make_float4(s[i][0], s[i][1], s[i][2], s[i][3]);
        }
        __syncthreads();

#pragma unroll 8
        for (int kk = 0; kk < 64; kk++) {
            float p0 = Ps[(ty * 4 + 0) * 64 + kk];
            float p1 = Ps[(ty * 4 + 1) * 64 + kk];
            float p2 = Ps[(ty * 4 + 2) * 64 + kk];
            float p3 = Ps[(ty * 4 + 3) * 64 + kk];
            float4 v4 = *(const float4*)(Vs + kk * 64 + tx * 4);
            o_acc[0][0] += p0 * v4.x; o_acc[0][1] += p0 * v4.y;
            o_acc[0][2] += p0 * v4.z; o_acc[0][3] += p0 * v4.w;
            o_acc[1][0] += p1 * v4.x; o_acc[1][1] += p1 * v4.y;
            o_acc[1][2] += p1 * v4.z; o_acc[1][3] += p1 * v4.w;
            o_acc[2][0] += p2 * v4.x; o_acc[2][1] += p2 * v4.y;
            o_acc[2][2] += p2 * v4.z; o_acc[2][3] += p2 * v4.w;
            o_acc[3][0] += p3 * v4.x; o_acc[3][1] += p3 * v4.y;
            o_acc[3][2] += p3 * v4.z; o_acc[3][3] += p3 * v4.w;
        }
    }

#pragma unroll
    for (int i = 0; i < 4; i++) {
        int qg = q0 + ty * 4 + i;
        if (qg < N_) {
            float inv = 1.f / l_row[i];
            float* orow = g_o + ((size_t)b * N_ + qg) * DIM_ + h * HD_;
#pragma unroll
            for (int j = 0; j < 4; j++) orow[tx * 4 + j] = o_acc[i][j] * inv;
        }
    }
}

// ---------------------------------------------------------------------------
extern "C" void kernel_launch(void* const* d_in, const int* in_sizes, int n_in,
                              void* d_out, int out_size) {
    (void)in_sizes; (void)n_in; (void)out_size;
    const float* x      = (const float*)d_in[0];
    const float* qkv_w  = (const float*)d_in[1];
    const float* proj_w = (const float*)d_in[2];
    const float* proj_b = (const float*)d_in[3];
    const float* rel_h  = (const float*)d_in[4];
    const float* rel_w  = (const float*)d_in[5];
    const float* rel_t  = (const float*)d_in[6];
    float* out = (float*)d_out;

    cudaFuncSetAttribute(attn_kernel,
                         cudaFuncAttributeMaxDynamicSharedMemorySize, (int)ATTN_SMEM);
    cudaFuncSetAttribute(mma_gemm,
                         cudaFuncAttributeMaxDynamicSharedMemorySize, GSMEM);

    const int nx  = MROWS * DIM_;           // 2,408,448
    const int nxp = MPAD * DIM_;            // 2,457,600
    const int nw  = 3 * DIM_ * DIM_;        // 1,769,472
    const int np  = DIM_ * DIM_;            // 589,824

    // 0) hi/lo split conversions for tensor-core inputs
    split_convert<<<(nxp + 255) / 256, 256>>>(x, 0, nx, nxp);
    split_convert<<<(nw + 255) / 256, 256>>>(qkv_w, 1, nw, nw);
    split_convert<<<(np + 255) / 256, 256>>>(proj_w, 2, np, np);

    // 1) QKV projection via mma.sync split-bf16 -> q/k/v scratch (head-major)
    mma_gemm<<<dim3(3 * DIM_ / 128, MPAD / 128), 256, GSMEM>>>(0, nullptr, nullptr);

    // 2) Decomposed rel-pos bias tables
    relbias<<<(B_ * HEADS_ * N_ + 7) / 8, 256>>>(rel_h, rel_w, rel_t);

    // 3) Fused attention (fp32 SIMT)
    attn_kernel<<<dim3((N_ + 63) / 64, HEADS_, B_), 256, ATTN_SMEM>>>();

    // 4) Split-convert attention output, then output projection via mma.sync
    split_convert<<<(nxp + 255) / 256, 256>>>(nullptr, 3, nx, nxp);
    mma_gemm<<<dim3(DIM_ / 128, MPAD / 128), 256, GSMEM>>>(1, proj_b, out);
}

// round 8
// speedup vs baseline: 2.7287x; 1.7851x over previous
#include <cuda_runtime.h>
#include <cuda_bf16.h>
#include <cstdint>

// Problem constants
#define B_     2
#define T_     8
#define H_     14
#define W_     14
#define S_     196          // H_*W_
#define N_     1568         // T_*S_
#define NPAD   1600         // padded rows per (b,h) for attention tiles
#define DIM_   768
#define HEADS_ 12
#define HD_    64
#define MROWS  (B_ * N_)    // 3136
#define MPAD   3200         // 25 * 128
#define NBIAS  36           // 14 (h) + 14 (w) + 8 (t)

// fp32 scratch
__device__ float g_q[(size_t)B_ * HEADS_ * N_ * HD_];
__device__ float g_k[(size_t)B_ * HEADS_ * N_ * HD_];
__device__ float g_v[(size_t)B_ * HEADS_ * N_ * HD_];
__device__ float g_bias[(size_t)B_ * HEADS_ * N_ * NBIAS];
__device__ float g_o[(size_t)MROWS * DIM_];

// split-bf16 scratch for the two projection GEMMs
__device__ __nv_bfloat16 g_xh[(size_t)MPAD * DIM_];
__device__ __nv_bfloat16 g_xl[(size_t)MPAD * DIM_];
__device__ __nv_bfloat16 g_wh[(size_t)3 * DIM_ * DIM_];
__device__ __nv_bfloat16 g_wl[(size_t)3 * DIM_ * DIM_];
__device__ __nv_bfloat16 g_ph[(size_t)DIM_ * DIM_];
__device__ __nv_bfloat16 g_pl[(size_t)DIM_ * DIM_];
__device__ __nv_bfloat16 g_oh[(size_t)MPAD * DIM_];
__device__ __nv_bfloat16 g_ol[(size_t)MPAD * DIM_];

// split-bf16 scratch for attention (padded to NPAD rows per (b,h); pad = 0)
#define ASZ ((size_t)B_ * HEADS_ * NPAD * HD_)
__device__ __nv_bfloat16 g_aqh[ASZ], g_aql[ASZ];   // Q pre-scaled by 0.125
__device__ __nv_bfloat16 g_akh[ASZ], g_akl[ASZ];
__device__ __nv_bfloat16 g_avh[ASZ], g_avl[ASZ];

// ---------------------------------------------------------------------------
// Helpers (sm_80-family only — compile clean to plain compute_103)
// ---------------------------------------------------------------------------
__device__ __forceinline__ uint32_t smem_u32(const void* p) {
    uint32_t a;
    asm("{ .reg .u64 t; cvta.to.shared.u64 t, %1; cvt.u32.u64 %0, t; }"
        : "=r"(a) : "l"(p));
    return a;
}

__device__ __forceinline__ uint32_t swz(uint32_t x) {
    return x ^ ((x >> 3) & 0x70);
}

#define CP_ASYNC16(s, g) \
    asm volatile("cp.async.cg.shared.global [%0], [%1], 16;" :: "r"(s), "l"(g))

#define LDSM4(r, a) \
    asm volatile("ldmatrix.sync.aligned.m8n8.x4.shared.b16 {%0,%1,%2,%3}, [%4];" \
        : "=r"((r)[0]), "=r"((r)[1]), "=r"((r)[2]), "=r"((r)[3]) : "r"(a))

#define LDSM4T(r, a) \
    asm volatile("ldmatrix.sync.aligned.m8n8.x4.trans.shared.b16 {%0,%1,%2,%3}, [%4];" \
        : "=r"((r)[0]), "=r"((r)[1]), "=r"((r)[2]), "=r"((r)[3]) : "r"(a))

#define MMA16816(d, a, b0, b1) \
    asm volatile("mma.sync.aligned.m16n8k16.row.col.f32.bf16.bf16.f32 " \
        "{%0,%1,%2,%3},{%4,%5,%6,%7},{%8,%9},{%0,%1,%2,%3};" \
        : "+f"((d)[0]), "+f"((d)[1]), "+f"((d)[2]), "+f"((d)[3]) \
        : "r"((a)[0]), "r"((a)[1]), "r"((a)[2]), "r"((a)[3]), "r"(b0), "r"(b1))

// pack two fp32 into bf16x2 hi/lo split (lo half = first arg)
__device__ __forceinline__ void split2(float p0, float p1,
                                       uint32_t& hi, uint32_t& lo) {
    __nv_bfloat16 h0 = __float2bfloat16(p0);
    __nv_bfloat16 h1 = __float2bfloat16(p1);
    __nv_bfloat162 hh; hh.x = h0; hh.y = h1;
    __nv_bfloat162 ll;
    ll.x = __float2bfloat16(p0 - __bfloat162float(h0));
    ll.y = __float2bfloat16(p1 - __bfloat162float(h1));
    hi = *reinterpret_cast<uint32_t*>(&hh);
    lo = *reinterpret_cast<uint32_t*>(&ll);
}

// ---------------------------------------------------------------------------
// Split conversion for GEMM operands.
// ---------------------------------------------------------------------------
__global__ __launch_bounds__(256) void split_convert(const float* __restrict__ src,
                                                     int sel, int n_src, int n_pad) {
    int i = blockIdx.x * blockDim.x + threadIdx.x;
    if (i >= n_pad) return;
    const float* s = (sel == 3) ? g_o : src;
    __nv_bfloat16 *hi, *lo;
    if (sel == 0)      { hi = g_xh; lo = g_xl; }
    else if (sel == 1) { hi = g_wh; lo = g_wl; }
    else if (sel == 2) { hi = g_ph; lo = g_pl; }
    else               { hi = g_oh; lo = g_ol; }
    float v = (i < n_src) ? s[i] : 0.f;
    __nv_bfloat16 h = __float2bfloat16(v);
    hi[i] = h;
    lo[i] = __float2bfloat16(v - __bfloat162float(h));
}

// Split conversion of q/k/v into padded attention layout. Q scaled by 0.125.
__global__ __launch_bounds__(256) void qkv_split() {
    int i = blockIdx.x * blockDim.x + threadIdx.x;
    if (i >= (int)(B_ * HEADS_ * NPAD * HD_)) return;
    int bh = i / (NPAD * HD_);
    int r = i - bh * (NPAD * HD_);
    int n = r >> 6;
    float qv = 0.f, kv = 0.f, vv = 0.f;
    if (n < N_) {
        size_t s = ((size_t)bh * N_ + n) * HD_ + (r & 63);
        qv = g_q[s] * 0.125f;
        kv = g_k[s];
        vv = g_v[s];
    }
    size_t o = (size_t)bh * NPAD * HD_ + r;
    __nv_bfloat16 h;
    h = __float2bfloat16(qv); g_aqh[o] = h;
    g_aql[o] = __float2bfloat16(qv - __bfloat162float(h));
    h = __float2bfloat16(kv); g_akh[o] = h;
    g_akl[o] = __float2bfloat16(kv - __bfloat162float(h));
    h = __float2bfloat16(vv); g_avh[o] = h;
    g_avl[o] = __float2bfloat16(vv - __bfloat162float(h));
}

// ---------------------------------------------------------------------------
// Warp-MMA split-bf16 GEMM (unchanged from R6; verified).
// ---------------------------------------------------------------------------
#define OFF_AH 0u
#define OFF_AL 16384u
#define OFF_BH 32768u
#define OFF_BL 49152u
#define GSMEM  65536

__global__ __launch_bounds__(256) void mma_gemm(int mode,
                                                const float* __restrict__ pb,
                                                float* __restrict__ out) {
    extern __shared__ char sm[];
    const uint32_t sb = smem_u32(sm);
    const int tid = threadIdx.x;
    const int lane = tid & 31, wid = tid >> 5;
    const int wm = wid & 3;
    const int wn = wid >> 2;
    const int m0 = blockIdx.y * 128;
    const int n0 = blockIdx.x * 128;

    const __nv_bfloat16* Ahp = (mode == 0) ? g_xh : g_oh;
    const __nv_bfloat16* Alp = (mode == 0) ? g_xl : g_ol;
    const __nv_bfloat16* Bhp = (mode == 0) ? g_wh : g_ph;
    const __nv_bfloat16* Blp = (mode == 0) ? g_wl : g_pl;

    float acc[2][8][4];
#pragma unroll
    for (int a = 0; a < 2; a++)
#pragma unroll
        for (int na = 0; na < 8; na++)
#pragma unroll
            for (int r = 0; r < 4; r++) acc[a][na][r] = 0.f;

    const int ar = lane & 15, akh = lane >> 4;
    const uint32_t a_base = (uint32_t)((wm * 32 + ar) * 128 + akh * 16);
    const int br = lane & 7, bsel = lane >> 3;
    const uint32_t b_base =
        (uint32_t)((wn * 64 + (bsel >> 1) * 8 + br) * 128 + (bsel & 1) * 16);

    const int grow = tid >> 3;
    const int gch = tid & 7;

    for (int c = 0; c < DIM_ / 64; c++) {
        const int k0 = c * 64;
#pragma unroll
        for (int p = 0; p < 4; p++) {
            int row = grow + p * 32;
            uint32_t sw = swz((uint32_t)(row * 128 + gch * 16));
            size_t ga = (size_t)(m0 + row) * DIM_ + k0 + gch * 8;
            size_t gb = (size_t)(n0 + row) * DIM_ + k0 + gch * 8;
            CP_ASYNC16(sb + OFF_AH + sw, Ahp + ga);
            CP_ASYNC16(sb + OFF_AL + sw, Alp + ga);
            CP_ASYNC16(sb + OFF_BH + sw, Bhp + gb);
            CP_ASYNC16(sb + OFF_BL + sw, Blp + gb);
        }
        asm volatile("cp.async.commit_group;");
        asm volatile("cp.async.wait_group 0;" ::: "memory");
        __syncthreads();

#pragma unroll
        for (int ks = 0; ks < 4; ks++) {
            const uint32_t kb = ks * 32;
            uint32_t ah[2][4], bh[4][4];
#pragma unroll
            for (int a = 0; a < 2; a++)
                LDSM4(ah[a], sb + OFF_AH + swz(a_base + a * 2048 + kb));
#pragma unroll
            for (int g = 0; g < 4; g++)
                LDSM4(bh[g], sb + OFF_BH + swz(b_base + g * 2048 + kb));
#pragma unroll
            for (int a = 0; a < 2; a++)
#pragma unroll
                for (int g = 0; g < 4; g++) {
                    MMA16816(acc[a][2 * g + 0], ah[a], bh[g][0], bh[g][1]);
                    MMA16816(acc[a][2 * g + 1], ah[a], bh[g][2], bh[g][3]);
                }
            {
                uint32_t al[2][4];
#pragma unroll
                for (int a = 0; a < 2; a++)
                    LDSM4(al[a], sb + OFF_AL + swz(a_base + a * 2048 + kb));
#pragma unroll
                for (int a = 0; a < 2; a++)
#pragma unroll
                    for (int g = 0; g < 4; g++) {
                        MMA16816(acc[a][2 * g + 0], al[a], bh[g][0], bh[g][1]);
                        MMA16816(acc[a][2 * g + 1], al[a], bh[g][2], bh[g][3]);
                    }
            }
#pragma unroll
            for (int g = 0; g < 4; g++)
                LDSM4(bh[g], sb + OFF_BL + swz(b_base + g * 2048 + kb));
#pragma unroll
            for (int a = 0; a < 2; a++)
#pragma unroll
                for (int g = 0; g < 4; g++) {
                    MMA16816(acc[a][2 * g + 0], ah[a], bh[g][0], bh[g][1]);
                    MMA16816(acc[a][2 * g + 1], ah[a], bh[g][2], bh[g][3]);
                }
        }
        __syncthreads();
    }

    const int mr = m0 + wm * 32 + lane / 4;
    const int nc0 = (lane & 3) * 2;
    if (mode == 0) {
        const int ncb = n0 + wn * 64;
        const int s = ncb / DIM_;
        const int head = (ncb % DIM_) / HD_;
        float* dst = (s == 0) ? g_q : (s == 1) ? g_k : g_v;
#pragma unroll
        for (int a = 0; a < 2; a++)
#pragma unroll
            for (int hf = 0; hf < 2; hf++) {
                int m = mr + a * 16 + hf * 8;
                if (m < MROWS) {
                    int bb = m / N_;
                    int nn = m - bb * N_;
                    float* drow = dst + (((size_t)bb * HEADS_ + head) * N_ + nn) * HD_;
#pragma unroll
                    for (int na = 0; na < 8; na++)
                        *(float2*)(drow + na * 8 + nc0) =
                            make_float2(acc[a][na][hf * 2], acc[a][na][hf * 2 + 1]);
                }
            }
    } else {
        const int ncb = n0 + wn * 64;
#pragma unroll
        for (int a = 0; a < 2; a++)
#pragma unroll
            for (int hf = 0; hf < 2; hf++) {
                int m = mr + a * 16 + hf * 8;
                if (m < MROWS) {
                    float* orow = out + (size_t)m * DIM_ + ncb;
#pragma unroll
                    for (int na = 0; na < 8; na++) {
                        int cc = na * 8 + nc0;
                        orow[cc]     = acc[a][na][hf * 2]     + pb[ncb + cc];
                        orow[cc + 1] = acc[a][na][hf * 2 + 1] + pb[ncb + cc + 1];
                    }
                }
            }
    }
}

// ---------------------------------------------------------------------------
// Relative position bias precompute (one warp per (b,h,q)).
// ---------------------------------------------------------------------------
__global__ __launch_bounds__(256) void relbias(const float* __restrict__ rel_h,
                                               const float* __restrict__ rel_w,
                                               const float* __restrict__ rel_t) {
    const int warp = (blockIdx.x * blockDim.x + threadIdx.x) >> 5;
    const int lane = threadIdx.x & 31;
    if (warp >= B_ * HEADS_ * N_) return;
    const int q = warp % N_;
    const int qt = q / S_;
    const int qrem = q - qt * S_;
    const int qh = qrem / W_;
    const int qw = qrem - qh * W_;

    const float* qv = g_q + (size_t)warp * HD_;
    const float qa = qv[lane];
    const float qb = qv[lane + 32];
    float* out = g_bias + (size_t)warp * NBIAS;

#pragma unroll 4
    for (int j = 0; j < NBIAS; j++) {
        const float* r;
        if (j < 14)       r = rel_h + (size_t)(qh - j + 13) * HD_;
        else if (j < 28)  r = rel_w + (size_t)(qw - (j - 14) + 13) * HD_;
        else              r = rel_t + (size_t)(qt - (j - 28) + 7) * HD_;
        float p = qa * r[lane] + qb * r[lane + 32];
#pragma unroll
        for (int m = 16; m >= 1; m >>= 1) p += __shfl_xor_sync(0xffffffffu, p, m);
        if (lane == 0) out[j] = p;
    }
}

// ---------------------------------------------------------------------------
// Tensor-core flash attention with decomposed rel-pos bias.
// Block = (b, h, 64-query tile), 4 warps (warp = 16 q rows), k-tiles of 64.
// QK^T: split-3 bf16 MMAs; softmax in fp32 fragments; P re-split in regs;
// PV: split-3 with V via ldmatrix.trans.
// ---------------------------------------------------------------------------
#define AT_KH 0u
#define AT_KL 8192u
#define AT_VH 16384u
#define AT_VL 24576u
#define AT_QH 32768u
#define AT_QL 40960u
#define AT_BI 49152u
#define AT_SMEM (49152 + 64 * NBIAS * 4)   // 58368

__global__ __launch_bounds__(128) void attn_tc() {
    extern __shared__ char sm[];
    const uint32_t sb = smem_u32(sm);
    float* Bi = (float*)(sm + AT_BI);
    const int b = blockIdx.z, h = blockIdx.y, q0 = blockIdx.x * 64;
    const int tid = threadIdx.x, lane = tid & 31, warp = tid >> 5;
    const size_t bh = (size_t)b * HEADS_ + h;
    const size_t abase = bh * NPAD * HD_;

    // Q tiles (hi/lo) via cp.async; Bi via plain loads
#pragma unroll
    for (int p = 0; p < 4; p++) {
        int idx = tid + p * 128;          // 0..511
        int row = idx >> 3, ch = idx & 7;
        uint32_t sw = swz((uint32_t)(row * 128 + ch * 16));
        size_t g = abase + (size_t)(q0 + row) * HD_ + ch * 8;
        CP_ASYNC16(sb + AT_QH + sw, g_aqh + g);
        CP_ASYNC16(sb + AT_QL + sw, g_aql + g);
    }
    for (int i = tid; i < 64 * NBIAS; i += 128) {
        int qr = i / NBIAS, qg = q0 + qr;
        Bi[i] = (qg < N_) ? g_bias[(bh * N_ + qg) * NBIAS + (i - qr * NBIAS)] : 0.f;
    }
    asm volatile("cp.async.commit_group;");
    asm volatile("cp.async.wait_group 0;" ::: "memory");
    __syncthreads();

    // Q fragments (held for the whole kernel)
    uint32_t qfh[4][4], qfl[4][4];
    {
        const uint32_t a_base =
            (uint32_t)((warp * 16 + (lane & 15)) * 128 + (lane >> 4) * 16);
#pragma unroll
        for (int kc = 0; kc < 4; kc++) {
            LDSM4(qfh[kc], sb + AT_QH + swz(a_base + kc * 32));
            LDSM4(qfl[kc], sb + AT_QL + swz(a_base + kc * 32));
        }
    }

    float oacc[8][4];
#pragma unroll
    for (int j = 0; j < 8; j++)
#pragma unroll
        for (int r = 0; r < 4; r++) oacc[j][r] = 0.f;
    float m0r = -1e30f, m1r = -1e30f, l0r = 0.f, l1r = 0.f;

    const uint32_t kb_base =
        (uint32_t)((((lane >> 4) * 8) + (lane & 7)) * 128 + ((lane >> 3) & 1) * 16);
    const int vr = (lane & 7) + ((lane >> 3) & 1) * 8;
    const uint32_t vcol = (uint32_t)((lane >> 4) * 16);
    const int r0q = warp * 16 + (lane >> 2);     // local q row (and +8)

    for (int kt = 0; kt < NPAD / 64; kt++) {
        const int k0 = kt * 64;
        // K/V hi/lo tiles (padded arrays: always in-bounds)
#pragma unroll
        for (int p = 0; p < 4; p++) {
            int idx = tid + p * 128;
            int row = idx >> 3, ch = idx & 7;
            uint32_t sw = swz((uint32_t)(row * 128 + ch * 16));
            size_t g = abase + (size_t)(k0 + row) * HD_ + ch * 8;
            CP_ASYNC16(sb + AT_KH + sw, g_akh + g);
            CP_ASYNC16(sb + AT_KL + sw, g_akl + g);
            CP_ASYNC16(sb + AT_VH + sw, g_avh + g);
            CP_ASYNC16(sb + AT_VL + sw, g_avl + g);
        }
        asm volatile("cp.async.commit_group;");
        asm volatile("cp.async.wait_group 0;" ::: "memory");
        __syncthreads();

        // ---- S = Qs K^T (split-3) ----
        float sacc[8][4];
#pragma unroll
        for (int j = 0; j < 8; j++)
#pragma unroll
            for (int r = 0; r < 4; r++) sacc[j][r] = 0.f;

#pragma unroll
        for (int kc = 0; kc < 4; kc++) {
            uint32_t kh4[4][4], kl4[4][4];
#pragma unroll
            for (int g = 0; g < 4; g++)
                LDSM4(kh4[g], sb + AT_KH + swz(kb_base + g * 2048 + kc * 32));
#pragma unroll
            for (int g = 0; g < 4; g++)
                LDSM4(kl4[g], sb + AT_KL + swz(kb_base + g * 2048 + kc * 32));
#pragma unroll
            for (int g = 0; g < 4; g++) {
                MMA16816(sacc[2 * g + 0], qfh[kc], kh4[g][0], kh4[g][1]);
                MMA16816(sacc[2 * g + 1], qfh[kc], kh4[g][2], kh4[g][3]);
                MMA16816(sacc[2 * g + 0], qfl[kc], kh4[g][0], kh4[g][1]);
                MMA16816(sacc[2 * g + 1], qfl[kc], kh4[g][2], kh4[g][3]);
                MMA16816(sacc[2 * g + 0], qfh[kc], kl4[g][0], kl4[g][1]);
                MMA16816(sacc[2 * g + 1], qfh[kc], kl4[g][2], kl4[g][3]);
            }
        }

        // ---- bias + mask ----
#pragma unroll
        for (int j = 0; j < 8; j++) {
#pragma unroll
            for (int c = 0; c < 2; c++) {
                int col = 8 * j + ((lane & 3) << 1) + c;
                int kg = k0 + col;
                if (kg < N_) {
                    int ktt = kg / S_;
                    int krem = kg - ktt * S_;
                    int khh = krem / W_;
                    int kww = krem - khh * W_;
                    const float* b0 = Bi + r0q * NBIAS;
                    const float* b1 = Bi + (r0q + 8) * NBIAS;
                    sacc[j][c]     += b0[khh] + b0[14 + kww] + b0[28 + ktt];
                    sacc[j][c + 2] += b1[khh] + b1[14 + kww] + b1[28 + ktt];
                } else {
                    sacc[j][c] = -1e30f;
                    sacc[j][c + 2] = -1e30f;
                }
            }
        }

        // ---- online softmax ----
        float mx0 = -1e30f, mx1 = -1e30f;
#pragma unroll
        for (int j = 0; j < 8; j++) {
            mx0 = fmaxf(mx0, fmaxf(sacc[j][0], sacc[j][1]));
            mx1 = fmaxf(mx1, fmaxf(sacc[j][2], sacc[j][3]));
        }
        mx0 = fmaxf(mx0, __shfl_xor_sync(0xffffffffu, mx0, 1));
        mx0 = fmaxf(mx0, __shfl_xor_sync(0xffffffffu, mx0, 2));
        mx1 = fmaxf(mx1, __shfl_xor_sync(0xffffffffu, mx1, 1));
        mx1 = fmaxf(mx1, __shfl_xor_sync(0xffffffffu, mx1, 2));
        float mn0 = fmaxf(m0r, mx0), mn1 = fmaxf(m1r, mx1);
        float cf0 = __expf(m0r - mn0), cf1 = __expf(m1r - mn1);
        m0r = mn0; m1r = mn1;
        float rs0 = 0.f, rs1 = 0.f;
#pragma unroll
        for (int j = 0; j < 8; j++) {
            sacc[j][0] = __expf(sacc[j][0] - mn0);
            sacc[j][1] = __expf(sacc[j][1] - mn0);
            sacc[j][2] = __expf(sacc[j][2] - mn1);
            sacc[j][3] = __expf(sacc[j][3] - mn1);
            rs0 += sacc[j][0] + sacc[j][1];
            rs1 += sacc[j][2] + sacc[j][3];
        }
        rs0 += __shfl_xor_sync(0xffffffffu, rs0, 1);
        rs0 += __shfl_xor_sync(0xffffffffu, rs0, 2);
        rs1 += __shfl_xor_sync(0xffffffffu, rs1, 1);
        rs1 += __shfl_xor_sync(0xffffffffu, rs1, 2);
        l0r = l0r * cf0 + rs0;
        l1r = l1r * cf1 + rs1;
#pragma unroll
        for (int j = 0; j < 8; j++) {
            oacc[j][0] *= cf0; oacc[j][1] *= cf0;
            oacc[j][2] *= cf1; oacc[j][3] *= cf1;
        }

        // ---- O += P V (split-3) ----
#pragma unroll
        for (int kc2 = 0; kc2 < 4; kc2++) {
            uint32_t ph[4], pl[4];
            split2(sacc[2 * kc2][0],     sacc[2 * kc2][1],     ph[0], pl[0]);
            split2(sacc[2 * kc2][2],     sacc[2 * kc2][3],     ph[1], pl[1]);
            split2(sacc[2 * kc2 + 1][0], sacc[2 * kc2 + 1][1], ph[2], pl[2]);
            split2(sacc[2 * kc2 + 1][2], sacc[2 * kc2 + 1][3], ph[3], pl[3]);
            const uint32_t vrow = (uint32_t)((kc2 * 16 + vr) * 128) + vcol;
#pragma unroll
            for (int g = 0; g < 4; g++) {
                uint32_t vh4[4], vl4[4];
                LDSM4T(vh4, sb + AT_VH + swz(vrow + g * 32));
                LDSM4T(vl4, sb + AT_VL + swz(vrow + g * 32));
                MMA16816(oacc[2 * g + 0], ph, vh4[0], vh4[1]);
                MMA16816(oacc[2 * g + 1], ph, vh4[2], vh4[3]);
                MMA16816(oacc[2 * g + 0], pl, vh4[0], vh4[1]);
                MMA16816(oacc[2 * g + 1], pl, vh4[2], vh4[3]);
                MMA16816(oacc[2 * g + 0], ph, vl4[0], vl4[1]);
                MMA16816(oacc[2 * g + 1], ph, vl4[2], vl4[3]);
            }
        }
        __syncthreads();
    }

    // ---- epilogue: O / l -> g_o [b][n][h*64 + d] ----
    const float inv0 = 1.f / l0r, inv1 = 1.f / l1r;
    const int qg0 = q0 + r0q;
#pragma unroll
    for (int j = 0; j < 8; j++) {
        int d = 8 * j + ((lane & 3) << 1);
        if (qg0 < N_) {
            float* p = g_o + ((size_t)b * N_ + qg0) * DIM_ + h * HD_ + d;
            p[0] = oacc[j][0] * inv0;
            p[1] = oacc[j][1] * inv0;
        }
        if (qg0 + 8 < N_) {
            float* p = g_o + ((size_t)b * N_ + qg0 + 8) * DIM_ + h * HD_ + d;
            p[0] = oacc[j][2] * inv1;
            p[1] = oacc[j][3] * inv1;
        }
    }
}

// ---------------------------------------------------------------------------
extern "C" void kernel_launch(void* const* d_in, const int* in_sizes, int n_in,
                              void* d_out, int out_size) {
    (void)in_sizes; (void)n_in; (void)out_size;
    const float* x      = (const float*)d_in[0];
    const float* qkv_w  = (const float*)d_in[1];
    const float* proj_w = (const float*)d_in[2];
    const float* proj_b = (const float*)d_in[3];
    const float* rel_h  = (const float*)d_in[4];
    const float* rel_w  = (const float*)d_in[5];
    const float* rel_t  = (const float*)d_in[6];
    float* out = (float*)d_out;

    cudaFuncSetAttribute(mma_gemm,
                         cudaFuncAttributeMaxDynamicSharedMemorySize, GSMEM);
    cudaFuncSetAttribute(attn_tc,
                         cudaFuncAttributeMaxDynamicSharedMemorySize, AT_SMEM);

    const int nx  = MROWS * DIM_;
    const int nxp = MPAD * DIM_;
    const int nw  = 3 * DIM_ * DIM_;
    const int np  = DIM_ * DIM_;
    const int na  = (int)(B_ * HEADS_ * NPAD * HD_);

    // 0) hi/lo split conversions for projection GEMMs
    split_convert<<<(nxp + 255) / 256, 256>>>(x, 0, nx, nxp);
    split_convert<<<(nw + 255) / 256, 256>>>(qkv_w, 1, nw, nw);
    split_convert<<<(np + 255) / 256, 256>>>(proj_w, 2, np, np);

    // 1) QKV projection -> fp32 q/k/v (head-major)
    mma_gemm<<<dim3(3 * DIM_ / 128, MPAD / 128), 256, GSMEM>>>(0, nullptr, nullptr);

    // 2) Decomposed rel-pos bias tables (unscaled q)
    relbias<<<(B_ * HEADS_ * N_ + 7) / 8, 256>>>(rel_h, rel_w, rel_t);

    // 3) hi/lo split of q (scaled), k, v into padded attention layout
    qkv_split<<<(na + 255) / 256, 256>>>();

    // 4) Tensor-core flash attention
    attn_tc<<<dim3(N_ / 64 + 1, HEADS_, B_), 128, AT_SMEM>>>();

    // 5) Output projection
    split_convert<<<(nxp + 255) / 256, 256>>>(nullptr, 3, nx, nxp);
    mma_gemm<<<dim3(DIM_ / 128, MPAD / 128), 256, GSMEM>>>(1, proj_b, out);
}

// round 10
// speedup vs baseline: 2.9723x; 1.0893x over previous
#include <cuda_runtime.h>
#include <cuda_bf16.h>
#include <cstdint>

// Problem constants
#define B_     2
#define T_     8
#define H_     14
#define W_     14
#define S_     196          // H_*W_
#define N_     1568         // T_*S_
#define NPAD   1600         // padded rows per (b,h) for attention tiles
#define DIM_   768
#define HEADS_ 12
#define HD_    64
#define MROWS  (B_ * N_)    // 3136
#define MPAD   3200         // 25 * 128
#define NBIAS  36           // 14 (h) + 14 (w) + 8 (t)

// fp32 scratch (q needed for relbias)
__device__ float g_q[(size_t)B_ * HEADS_ * N_ * HD_];
__device__ float g_bias[(size_t)B_ * HEADS_ * N_ * NBIAS];

// split-bf16 scratch for the two projection GEMMs
__device__ __nv_bfloat16 g_xh[(size_t)MPAD * DIM_];
__device__ __nv_bfloat16 g_xl[(size_t)MPAD * DIM_];
__device__ __nv_bfloat16 g_wh[(size_t)3 * DIM_ * DIM_];
__device__ __nv_bfloat16 g_wl[(size_t)3 * DIM_ * DIM_];
__device__ __nv_bfloat16 g_ph[(size_t)DIM_ * DIM_];
__device__ __nv_bfloat16 g_pl[(size_t)DIM_ * DIM_];
// attention output, split (pad rows stay statically zero — never written)
__device__ __nv_bfloat16 g_oh[(size_t)MPAD * DIM_];
__device__ __nv_bfloat16 g_ol[(size_t)MPAD * DIM_];

// split-bf16 attention operands (padded; pad rows statically zero)
#define ASZ ((size_t)B_ * HEADS_ * NPAD * HD_)
__device__ __nv_bfloat16 g_aqh[ASZ], g_aql[ASZ];   // Q pre-scaled by 0.125
__device__ __nv_bfloat16 g_akh[ASZ], g_akl[ASZ];
__device__ __nv_bfloat16 g_avh[ASZ], g_avl[ASZ];

// ---------------------------------------------------------------------------
// Helpers (sm_80-family only — compile clean to plain compute_103)
// ---------------------------------------------------------------------------
__device__ __forceinline__ uint32_t smem_u32(const void* p) {
    uint32_t a;
    asm("{ .reg .u64 t; cvta.to.shared.u64 t, %1; cvt.u32.u64 %0, t; }"
        : "=r"(a) : "l"(p));
    return a;
}

__device__ __forceinline__ uint32_t swz(uint32_t x) {
    return x ^ ((x >> 3) & 0x70);
}

#define CP_ASYNC16(s, g) \
    asm volatile("cp.async.cg.shared.global [%0], [%1], 16;" :: "r"(s), "l"(g))

#define LDSM4(r, a) \
    asm volatile("ldmatrix.sync.aligned.m8n8.x4.shared.b16 {%0,%1,%2,%3}, [%4];" \
        : "=r"((r)[0]), "=r"((r)[1]), "=r"((r)[2]), "=r"((r)[3]) : "r"(a))

#define LDSM4T(r, a) \
    asm volatile("ldmatrix.sync.aligned.m8n8.x4.trans.shared.b16 {%0,%1,%2,%3}, [%4];" \
        : "=r"((r)[0]), "=r"((r)[1]), "=r"((r)[2]), "=r"((r)[3]) : "r"(a))

#define MMA16816(d, a, b0, b1) \
    asm volatile("mma.sync.aligned.m16n8k16.row.col.f32.bf16.bf16.f32 " \
        "{%0,%1,%2,%3},{%4,%5,%6,%7},{%8,%9},{%0,%1,%2,%3};" \
        : "+f"((d)[0]), "+f"((d)[1]), "+f"((d)[2]), "+f"((d)[3]) \
        : "r"((a)[0]), "r"((a)[1]), "r"((a)[2]), "r"((a)[3]), "r"(b0), "r"(b1))

// pack two fp32 into bf16x2 hi/lo split
__device__ __forceinline__ void split2(float p0, float p1,
                                       uint32_t& hi, uint32_t& lo) {
    __nv_bfloat16 h0 = __float2bfloat16(p0);
    __nv_bfloat16 h1 = __float2bfloat16(p1);
    __nv_bfloat162 hh; hh.x = h0; hh.y = h1;
    __nv_bfloat162 ll;
    ll.x = __float2bfloat16(p0 - __bfloat162float(h0));
    ll.y = __float2bfloat16(p1 - __bfloat162float(h1));
    hi = *reinterpret_cast<uint32_t*>(&hh);
    lo = *reinterpret_cast<uint32_t*>(&ll);
}

// ---------------------------------------------------------------------------
// Split conversion for GEMM inputs (x, qkv_w, proj_w).
// ---------------------------------------------------------------------------
__global__ __launch_bounds__(256) void split_convert(const float* __restrict__ src,
                                                     int sel, int n_src, int n_pad) {
    int i = blockIdx.x * blockDim.x + threadIdx.x;
    if (i >= n_pad) return;
    __nv_bfloat16 *hi, *lo;
    if (sel == 0)      { hi = g_xh; lo = g_xl; }
    else if (sel == 1) { hi = g_wh; lo = g_wl; }
    else               { hi = g_ph; lo = g_pl; }
    float v = (i < n_src) ? src[i] : 0.f;
    __nv_bfloat16 h = __float2bfloat16(v);
    hi[i] = h;
    lo[i] = __float2bfloat16(v - __bfloat162float(h));
}

// ---------------------------------------------------------------------------
// Warp-MMA split-bf16 GEMM, double-buffered K-chunks.
// CTA tile 128x128, 8 warps (32m x 64n each), K chunks of 64, 2 smem stages.
// mode 0: A=x, B=qkv_w -> epilogue writes fp32 g_q + split q/k/v attn arrays.
// mode 1: A=g_oh/ol, B=proj_w -> epilogue adds proj_b, writes out.
// ---------------------------------------------------------------------------
#define OFF_AH 0u
#define OFF_AL 16384u
#define OFF_BH 32768u
#define OFF_BL 49152u
#define GSTAGE 65536u
#define GSMEM  131072

__device__ __forceinline__ void gemm_load(uint32_t sb, uint32_t so,
        const __nv_bfloat16* Ahp, const __nv_bfloat16* Alp,
        const __nv_bfloat16* Bhp, const __nv_bfloat16* Blp,
        int m0, int n0, int k0, int tid) {
    const int grow = tid >> 3, gch = tid & 7;
#pragma unroll
    for (int p = 0; p < 4; p++) {
        int row = grow + p * 32;
        uint32_t sw = swz((uint32_t)(row * 128 + gch * 16));
        size_t ga = (size_t)(m0 + row) * DIM_ + k0 + gch * 8;
        size_t gb = (size_t)(n0 + row) * DIM_ + k0 + gch * 8;
        CP_ASYNC16(sb + so + OFF_AH + sw, Ahp + ga);
        CP_ASYNC16(sb + so + OFF_AL + sw, Alp + ga);
        CP_ASYNC16(sb + so + OFF_BH + sw, Bhp + gb);
        CP_ASYNC16(sb + so + OFF_BL + sw, Blp + gb);
    }
    asm volatile("cp.async.commit_group;");
}

__global__ __launch_bounds__(256) void mma_gemm(int mode,
                                                const float* __restrict__ pb,
                                                float* __restrict__ out) {
    extern __shared__ char sm[];
    const uint32_t sb = smem_u32(sm);
    const int tid = threadIdx.x;
    const int lane = tid & 31, wid = tid >> 5;
    const int wm = wid & 3;
    const int wn = wid >> 2;
    const int m0 = blockIdx.y * 128;
    const int n0 = blockIdx.x * 128;

    const __nv_bfloat16* Ahp = (mode == 0) ? g_xh : g_oh;
    const __nv_bfloat16* Alp = (mode == 0) ? g_xl : g_ol;
    const __nv_bfloat16* Bhp = (mode == 0) ? g_wh : g_ph;
    const __nv_bfloat16* Blp = (mode == 0) ? g_wl : g_pl;

    float acc[2][8][4];
#pragma unroll
    for (int a = 0; a < 2; a++)
#pragma unroll
        for (int na = 0; na < 8; na++)
#pragma unroll
            for (int r = 0; r < 4; r++) acc[a][na][r] = 0.f;

    const int ar = lane & 15, akh = lane >> 4;
    const uint32_t a_base = (uint32_t)((wm * 32 + ar) * 128 + akh * 16);
    const int br = lane & 7, bsel = lane >> 3;
    const uint32_t b_base =
        (uint32_t)((wn * 64 + (bsel >> 1) * 8 + br) * 128 + (bsel & 1) * 16);

    // Prologue: chunk 0 -> stage 0
    gemm_load(sb, 0u, Ahp, Alp, Bhp, Blp, m0, n0, 0, tid);

    for (int c = 0; c < DIM_ / 64; c++) {
        const uint32_t so = (uint32_t)(c & 1) * GSTAGE;
        if (c + 1 < DIM_ / 64) {
            gemm_load(sb, (uint32_t)((c + 1) & 1) * GSTAGE,
                      Ahp, Alp, Bhp, Blp, m0, n0, (c + 1) * 64, tid);
            asm volatile("cp.async.wait_group 1;" ::: "memory");
        } else {
            asm volatile("cp.async.wait_group 0;" ::: "memory");
        }
        __syncthreads();

#pragma unroll
        for (int ks = 0; ks < 4; ks++) {
            const uint32_t kb = ks * 32;
            uint32_t ah[2][4], bh[4][4];
#pragma unroll
            for (int a = 0; a < 2; a++)
                LDSM4(ah[a], sb + so + OFF_AH + swz(a_base + a * 2048 + kb));
#pragma unroll
            for (int g = 0; g < 4; g++)
                LDSM4(bh[g], sb + so + OFF_BH + swz(b_base + g * 2048 + kb));
#pragma unroll
            for (int a = 0; a < 2; a++)
#pragma unroll
                for (int g = 0; g < 4; g++) {
                    MMA16816(acc[a][2 * g + 0], ah[a], bh[g][0], bh[g][1]);
                    MMA16816(acc[a][2 * g + 1], ah[a], bh[g][2], bh[g][3]);
                }
            {
                uint32_t al[2][4];
#pragma unroll
                for (int a = 0; a < 2; a++)
                    LDSM4(al[a], sb + so + OFF_AL + swz(a_base + a * 2048 + kb));
#pragma unroll
                for (int a = 0; a < 2; a++)
#pragma unroll
                    for (int g = 0; g < 4; g++) {
                        MMA16816(acc[a][2 * g + 0], al[a], bh[g][0], bh[g][1]);
                        MMA16816(acc[a][2 * g + 1], al[a], bh[g][2], bh[g][3]);
                    }
            }
#pragma unroll
            for (int g = 0; g < 4; g++)
                LDSM4(bh[g], sb + so + OFF_BL + swz(b_base + g * 2048 + kb));
#pragma unroll
            for (int a = 0; a < 2; a++)
#pragma unroll
                for (int g = 0; g < 4; g++) {
                    MMA16816(acc[a][2 * g + 0], ah[a], bh[g][0], bh[g][1]);
                    MMA16816(acc[a][2 * g + 1], ah[a], bh[g][2], bh[g][3]);
                }
        }
        __syncthreads();
    }

    const int mr = m0 + wm * 32 + lane / 4;
    const int nc0 = (lane & 3) * 2;
    if (mode == 0) {
        const int ncb = n0 + wn * 64;
        const int s = ncb / DIM_;                 // 0=q,1=k,2=v
        const int head = (ncb % DIM_) / HD_;
#pragma unroll
        for (int a = 0; a < 2; a++)
#pragma unroll
            for (int hf = 0; hf < 2; hf++) {
                int m = mr + a * 16 + hf * 8;
                if (m < MROWS) {
                    int bb = m / N_;
                    int nn = m - bb * N_;
                    size_t bh = (size_t)bb * HEADS_ + head;
                    size_t arow = (bh * NPAD + nn) * HD_;
#pragma unroll
                    for (int na = 0; na < 8; na++) {
                        int col = na * 8 + nc0;
                        float v0 = acc[a][na][hf * 2];
                        float v1 = acc[a][na][hf * 2 + 1];
                        uint32_t hi, lo;
                        if (s == 0) {
                            float* qrow = g_q + (bh * N_ + nn) * HD_;
                            qrow[col] = v0; qrow[col + 1] = v1;   // unscaled (relbias)
                            split2(v0 * 0.125f, v1 * 0.125f, hi, lo);
                            *(uint32_t*)(g_aqh + arow + col) = hi;
                            *(uint32_t*)(g_aql + arow + col) = lo;
                        } else if (s == 1) {
                            split2(v0, v1, hi, lo);
                            *(uint32_t*)(g_akh + arow + col) = hi;
                            *(uint32_t*)(g_akl + arow + col) = lo;
                        } else {
                            split2(v0, v1, hi, lo);
                            *(uint32_t*)(g_avh + arow + col) = hi;
                            *(uint32_t*)(g_avl + arow + col) = lo;
                        }
                    }
                }
            }
    } else {
        const int ncb = n0 + wn * 64;
#pragma unroll
        for (int a = 0; a < 2; a++)
#pragma unroll
            for (int hf = 0; hf < 2; hf++) {
                int m = mr + a * 16 + hf * 8;
                if (m < MROWS) {
                    float* orow = out + (size_t)m * DIM_ + ncb;
#pragma unroll
                    for (int na = 0; na < 8; na++) {
                        int cc = na * 8 + nc0;
                        orow[cc]     = acc[a][na][hf * 2]     + pb[ncb + cc];
                        orow[cc + 1] = acc[a][na][hf * 2 + 1] + pb[ncb + cc + 1];
                    }
                }
            }
    }
}

// ---------------------------------------------------------------------------
// Relative position bias precompute (one warp per (b,h,q); unscaled q).
// ---------------------------------------------------------------------------
__global__ __launch_bounds__(256) void relbias(const float* __restrict__ rel_h,
                                               const float* __restrict__ rel_w,
                                               const float* __restrict__ rel_t) {
    const int warp = (blockIdx.x * blockDim.x + threadIdx.x) >> 5;
    const int lane = threadIdx.x & 31;
    if (warp >= B_ * HEADS_ * N_) return;
    const int q = warp % N_;
    const int qt = q / S_;
    const int qrem = q - qt * S_;
    const int qh = qrem / W_;
    const int qw = qrem - qh * W_;

    const float* qv = g_q + (size_t)warp * HD_;
    const float qa = qv[lane];
    const float qb = qv[lane + 32];
    float* out = g_bias + (size_t)warp * NBIAS;

#pragma unroll 4
    for (int j = 0; j < NBIAS; j++) {
        const float* r;
        if (j < 14)       r = rel_h + (size_t)(qh - j + 13) * HD_;
        else if (j < 28)  r = rel_w + (size_t)(qw - (j - 14) + 13) * HD_;
        else              r = rel_t + (size_t)(qt - (j - 28) + 7) * HD_;
        float p = qa * r[lane] + qb * r[lane + 32];
#pragma unroll
        for (int m = 16; m >= 1; m >>= 1) p += __shfl_xor_sync(0xffffffffu, p, m);
        if (lane == 0) out[j] = p;
    }
}

// ---------------------------------------------------------------------------
// Tensor-core flash attention, double-buffered K/V tiles.
// Block = (b, h, 64-query tile), 4 warps, k-tiles of 64, 2 smem stages.
// Epilogue writes split-bf16 O directly (g_oh/g_ol).
// ---------------------------------------------------------------------------
#define AT_KH 0u
#define AT_KL 8192u
#define AT_VH 16384u
#define AT_VL 24576u
#define AT_STAGE 32768u
#define AT_QH 65536u
#define AT_QL 73728u
#define AT_BI 81920u
#define AT_SMEM (81920 + 64 * NBIAS * 4)   // 91136

__device__ __forceinline__ void attn_load_kv(uint32_t sb, uint32_t so,
                                             size_t abase, int k0, int tid) {
#pragma unroll
    for (int p = 0; p < 4; p++) {
        int idx = tid + p * 128;
        int row = idx >> 3, ch = idx & 7;
        uint32_t sw = swz((uint32_t)(row * 128 + ch * 16));
        size_t g = abase + (size_t)(k0 + row) * HD_ + ch * 8;
        CP_ASYNC16(sb + so + AT_KH + sw, g_akh + g);
        CP_ASYNC16(sb + so + AT_KL + sw, g_akl + g);
        CP_ASYNC16(sb + so + AT_VH + sw, g_avh + g);
        CP_ASYNC16(sb + so + AT_VL + sw, g_avl + g);
    }
    asm volatile("cp.async.commit_group;");
}

__global__ __launch_bounds__(128) void attn_tc() {
    extern __shared__ char sm[];
    const uint32_t sb = smem_u32(sm);
    float* Bi = (float*)(sm + AT_BI);
    const int b = blockIdx.z, h = blockIdx.y, q0 = blockIdx.x * 64;
    const int tid = threadIdx.x, lane = tid & 31, warp = tid >> 5;
    const size_t bh = (size_t)b * HEADS_ + h;
    const size_t abase = bh * NPAD * HD_;
    const int NT = NPAD / 64;                 // 25 k-tiles

    // Group A: Q tiles (hi/lo) + KV tile 0 (stage 0)
#pragma unroll
    for (int p = 0; p < 4; p++) {
        int idx = tid + p * 128;
        int row = idx >> 3, ch = idx & 7;
        uint32_t sw = swz((uint32_t)(row * 128 + ch * 16));
        size_t g = abase + (size_t)(q0 + row) * HD_ + ch * 8;
        CP_ASYNC16(sb + AT_QH + sw, g_aqh + g);
        CP_ASYNC16(sb + AT_QL + sw, g_aql + g);
        size_t gk = abase + (size_t)row * HD_ + ch * 8;
        CP_ASYNC16(sb + AT_KH + sw, g_akh + gk);
        CP_ASYNC16(sb + AT_KL + sw, g_akl + gk);
        CP_ASYNC16(sb + AT_VH + sw, g_avh + gk);
        CP_ASYNC16(sb + AT_VL + sw, g_avl + gk);
    }
    for (int i = tid; i < 64 * NBIAS; i += 128) {
        int qr = i / NBIAS, qg = q0 + qr;
        Bi[i] = (qg < N_) ? g_bias[(bh * N_ + qg) * NBIAS + (i - qr * NBIAS)] : 0.f;
    }
    asm volatile("cp.async.commit_group;");
    // Group B: prefetch KV tile 1 (stage 1)
    attn_load_kv(sb, AT_STAGE, abase, 64, tid);
    asm volatile("cp.async.wait_group 1;" ::: "memory");   // group A done
    __syncthreads();

    // Q fragments (held for the whole kernel)
    uint32_t qfh[4][4], qfl[4][4];
    {
        const uint32_t a_base =
            (uint32_t)((warp * 16 + (lane & 15)) * 128 + (lane >> 4) * 16);
#pragma unroll
        for (int kc = 0; kc < 4; kc++) {
            LDSM4(qfh[kc], sb + AT_QH + swz(a_base + kc * 32));
            LDSM4(qfl[kc], sb + AT_QL + swz(a_base + kc * 32));
        }
    }

    float oacc[8][4];
#pragma unroll
    for (int j = 0; j < 8; j++)
#pragma unroll
        for (int r = 0; r < 4; r++) oacc[j][r] = 0.f;
    float m0r = -1e30f, m1r = -1e30f, l0r = 0.f, l1r = 0.f;

    const uint32_t kb_base =
        (uint32_t)((((lane >> 4) * 8) + (lane & 7)) * 128 + ((lane >> 3) & 1) * 16);
    const int vr = (lane & 7) + ((lane >> 3) & 1) * 8;
    const uint32_t vcol = (uint32_t)((lane >> 4) * 16);
    const int r0q = warp * 16 + (lane >> 2);

    for (int kt = 0; kt < NT; kt++) {
        const int k0 = kt * 64;
        const uint32_t so = (uint32_t)(kt & 1) * AT_STAGE;
        if (kt >= 1) {
            if (kt + 1 < NT) {
                attn_load_kv(sb, (uint32_t)((kt + 1) & 1) * AT_STAGE,
                             abase, (kt + 1) * 64, tid);
                asm volatile("cp.async.wait_group 1;" ::: "memory");
            } else {
                asm volatile("cp.async.wait_group 0;" ::: "memory");
            }
            __syncthreads();
        }

        // ---- S = Qs K^T (split-3) ----
        float sacc[8][4];
#pragma unroll
        for (int j = 0; j < 8; j++)
#pragma unroll
            for (int r = 0; r < 4; r++) sacc[j][r] = 0.f;

#pragma unroll
        for (int kc = 0; kc < 4; kc++) {
            uint32_t kh4[4][4], kl4[4][4];
#pragma unroll
            for (int g = 0; g < 4; g++)
                LDSM4(kh4[g], sb + so + AT_KH + swz(kb_base + g * 2048 + kc * 32));
#pragma unroll
            for (int g = 0; g < 4; g++)
                LDSM4(kl4[g], sb + so + AT_KL + swz(kb_base + g * 2048 + kc * 32));
#pragma unroll
            for (int g = 0; g < 4; g++) {
                MMA16816(sacc[2 * g + 0], qfh[kc], kh4[g][0], kh4[g][1]);
                MMA16816(sacc[2 * g + 1], qfh[kc], kh4[g][2], kh4[g][3]);
                MMA16816(sacc[2 * g + 0], qfl[kc], kh4[g][0], kh4[g][1]);
                MMA16816(sacc[2 * g + 1], qfl[kc], kh4[g][2], kh4[g][3]);
                MMA16816(sacc[2 * g + 0], qfh[kc], kl4[g][0], kl4[g][1]);
                MMA16816(sacc[2 * g + 1], qfh[kc], kl4[g][2], kl4[g][3]);
            }
        }

        // ---- bias + mask ----
#pragma unroll
        for (int j = 0; j < 8; j++) {
#pragma unroll
            for (int c = 0; c < 2; c++) {
                int col = 8 * j + ((lane & 3) << 1) + c;
                int kg = k0 + col;
                if (kg < N_) {
                    int ktt = kg / S_;
                    int krem = kg - ktt * S_;
                    int khh = krem / W_;
                    int kww = krem - khh * W_;
                    const float* b0 = Bi + r0q * NBIAS;
                    const float* b1 = Bi + (r0q + 8) * NBIAS;
                    sacc[j][c]     += b0[khh] + b0[14 + kww] + b0[28 + ktt];
                    sacc[j][c + 2] += b1[khh] + b1[14 + kww] + b1[28 + ktt];
                } else {
                    sacc[j][c] = -1e30f;
                    sacc[j][c + 2] = -1e30f;
                }
            }
        }

        // ---- online softmax ----
        float mx0 = -1e30f, mx1 = -1e30f;
#pragma unroll
        for (int j = 0; j < 8; j++) {
            mx0 = fmaxf(mx0, fmaxf(sacc[j][0], sacc[j][1]));
            mx1 = fmaxf(mx1, fmaxf(sacc[j][2], sacc[j][3]));
        }
        mx0 = fmaxf(mx0, __shfl_xor_sync(0xffffffffu, mx0, 1));
        mx0 = fmaxf(mx0, __shfl_xor_sync(0xffffffffu, mx0, 2));
        mx1 = fmaxf(mx1, __shfl_xor_sync(0xffffffffu, mx1, 1));
        mx1 = fmaxf(mx1, __shfl_xor_sync(0xffffffffu, mx1, 2));
        float mn0 = fmaxf(m0r, mx0), mn1 = fmaxf(m1r, mx1);
        float cf0 = __expf(m0r - mn0), cf1 = __expf(m1r - mn1);
        m0r = mn0; m1r = mn1;
        float rs0 = 0.f, rs1 = 0.f;
#pragma unroll
        for (int j = 0; j < 8; j++) {
            sacc[j][0] = __expf(sacc[j][0] - mn0);
            sacc[j][1] = __expf(sacc[j][1] - mn0);
            sacc[j][2] = __expf(sacc[j][2] - mn1);
            sacc[j][3] = __expf(sacc[j][3] - mn1);
            rs0 += sacc[j][0] + sacc[j][1];
            rs1 += sacc[j][2] + sacc[j][3];
        }
        rs0 += __shfl_xor_sync(0xffffffffu, rs0, 1);
        rs0 += __shfl_xor_sync(0xffffffffu, rs0, 2);
        rs1 += __shfl_xor_sync(0xffffffffu, rs1, 1);
        rs1 += __shfl_xor_sync(0xffffffffu, rs1, 2);
        l0r = l0r * cf0 + rs0;
        l1r = l1r * cf1 + rs1;
#pragma unroll
        for (int j = 0; j < 8; j++) {
            oacc[j][0] *= cf0; oacc[j][1] *= cf0;
            oacc[j][2] *= cf1; oacc[j][3] *= cf1;
        }

        // ---- O += P V (split-3) ----
#pragma unroll
        for (int kc2 = 0; kc2 < 4; kc2++) {
            uint32_t ph[4], pl[4];
            split2(sacc[2 * kc2][0],     sacc[2 * kc2][1],     ph[0], pl[0]);
            split2(sacc[2 * kc2][2],     sacc[2 * kc2][3],     ph[1], pl[1]);
            split2(sacc[2 * kc2 + 1][0], sacc[2 * kc2 + 1][1], ph[2], pl[2]);
            split2(sacc[2 * kc2 + 1][2], sacc[2 * kc2 + 1][3], ph[3], pl[3]);
            const uint32_t vrow = (uint32_t)((kc2 * 16 + vr) * 128) + vcol;
#pragma unroll
            for (int g = 0; g < 4; g++) {
                uint32_t vh4[4], vl4[4];
                LDSM4T(vh4, sb + so + AT_VH + swz(vrow + g * 32));
                LDSM4T(vl4, sb + so + AT_VL + swz(vrow + g * 32));
                MMA16816(oacc[2 * g + 0], ph, vh4[0], vh4[1]);
                MMA16816(oacc[2 * g + 1], ph, vh4[2], vh4[3]);
                MMA16816(oacc[2 * g + 0], pl, vh4[0], vh4[1]);
                MMA16816(oacc[2 * g + 1], pl, vh4[2], vh4[3]);
                MMA16816(oacc[2 * g + 0], ph, vl4[0], vl4[1]);
                MMA16816(oacc[2 * g + 1], ph, vl4[2], vl4[3]);
            }
        }
        __syncthreads();
    }

    // ---- epilogue: O / l -> split bf16 g_oh/g_ol at [b*N+q][h*64+d] ----
    const float inv0 = 1.f / l0r, inv1 = 1.f / l1r;
    const int qg0 = q0 + r0q;
#pragma unroll
    for (int j = 0; j < 8; j++) {
        int d = 8 * j + ((lane & 3) << 1);
        if (qg0 < N_) {
            size_t off = ((size_t)b * N_ + qg0) * DIM_ + h * HD_ + d;
            uint32_t hi, lo;
            split2(oacc[j][0] * inv0, oacc[j][1] * inv0, hi, lo);
            *(uint32_t*)(g_oh + off) = hi;
            *(uint32_t*)(g_ol + off) = lo;
        }
        if (qg0 + 8 < N_) {
            size_t off = ((size_t)b * N_ + qg0 + 8) * DIM_ + h * HD_ + d;
            uint32_t hi, lo;
            split2(oacc[j][2] * inv1, oacc[j][3] * inv1, hi, lo);
            *(uint32_t*)(g_oh + off) = hi;
            *(uint32_t*)(g_ol + off) = lo;
        }
    }
}

// ---------------------------------------------------------------------------
extern "C" void kernel_launch(void* const* d_in, const int* in_sizes, int n_in,
                              void* d_out, int out_size) {
    (void)in_sizes; (void)n_in; (void)out_size;
    const float* x      = (const float*)d_in[0];
    const float* qkv_w  = (const float*)d_in[1];
    const float* proj_w = (const float*)d_in[2];
    const float* proj_b = (const float*)d_in[3];
    const float* rel_h  = (const float*)d_in[4];
    const float* rel_w  = (const float*)d_in[5];
    const float* rel_t  = (const float*)d_in[6];
    float* out = (float*)d_out;

    cudaFuncSetAttribute(mma_gemm,
                         cudaFuncAttributeMaxDynamicSharedMemorySize, GSMEM);
    cudaFuncSetAttribute(attn_tc,
                         cudaFuncAttributeMaxDynamicSharedMemorySize, AT_SMEM);

    const int nx  = MROWS * DIM_;
    const int nxp = MPAD * DIM_;
    const int nw  = 3 * DIM_ * DIM_;
    const int np  = DIM_ * DIM_;

    // 0) hi/lo split conversions for GEMM inputs
    split_convert<<<(nxp + 255) / 256, 256>>>(x, 0, nx, nxp);
    split_convert<<<(nw + 255) / 256, 256>>>(qkv_w, 1, nw, nw);
    split_convert<<<(np + 255) / 256, 256>>>(proj_w, 2, np, np);

    // 1) QKV projection -> fp32 g_q + split q/k/v attention arrays (fused)
    mma_gemm<<<dim3(3 * DIM_ / 128, MPAD / 128), 256, GSMEM>>>(0, nullptr, nullptr);

    // 2) Decomposed rel-pos bias tables (unscaled q)
    relbias<<<(B_ * HEADS_ * N_ + 7) / 8, 256>>>(rel_h, rel_w, rel_t);

    // 3) Tensor-core flash attention -> split g_oh/g_ol (fused epilogue)
    attn_tc<<<dim3(NPAD / 64, HEADS_, B_), 128, AT_SMEM>>>();

    // 4) Output projection
    mma_gemm<<<dim3(DIM_ / 128, MPAD / 128), 256, GSMEM>>>(1, proj_b, out);
}